// round 17
// baseline (speedup 1.0000x reference)
#include <cuda_runtime.h>
#include <cuda_bf16.h>
#include <stdint.h>

#define NB 8
#define NS 128
#define ND 512
#define NL 512
#define NR 50
#define NBS 1024
#define OUT_HEAD (NB*NS*NS)

__device__ __align__(1024) float g_P[8][NBS][NL];
__device__ __align__(1024) __nv_bfloat16 g_Xhi[NBS][ND];
__device__ __align__(1024) __nv_bfloat16 g_Xlo[NBS][ND];
__device__ __align__(1024) __nv_bfloat16 g_Wthi[8][NL][ND];   // [z][n][k]
__device__ __align__(1024) __nv_bfloat16 g_Wtlo[8][NL][ND];
__device__ __align__(1024) __nv_bfloat16 g_W2thi[64][NL];     // [o][l], o padded to 64
__device__ __align__(1024) __nv_bfloat16 g_W2tlo[64][NL];

struct ProjArgs { const float* W1[4]; const float* b1[4]; };
struct ScalArgs { const float* w2[3]; const float* b2[3]; };

__device__ __forceinline__ float tanha(float x) {
    float y; asm("tanh.approx.f32 %0, %1;" : "=f"(y) : "f"(x)); return y;
}
__device__ __forceinline__ uint32_t s2u(const void* p) {
    uint32_t a;
    asm("{ .reg .u64 t; cvta.to.shared.u64 t, %1; cvt.u32.u64 %0, t; }" : "=r"(a) : "l"(p));
    return a;
}
__device__ __forceinline__ void ldm4(uint32_t* r, uint32_t a) {
    asm volatile("ldmatrix.sync.aligned.m8n8.x4.shared.b16 {%0,%1,%2,%3}, [%4];"
        : "=r"(r[0]), "=r"(r[1]), "=r"(r[2]), "=r"(r[3]) : "r"(a));
}
__device__ __forceinline__ void mma_bb(float* c, const uint32_t* a, const uint32_t* b) {
    asm volatile("mma.sync.aligned.m16n8k16.row.col.f32.bf16.bf16.f32 "
        "{%0,%1,%2,%3}, {%4,%5,%6,%7}, {%8,%9}, {%0,%1,%2,%3};"
        : "+f"(c[0]), "+f"(c[1]), "+f"(c[2]), "+f"(c[3])
        : "r"(a[0]), "r"(a[1]), "r"(a[2]), "r"(a[3]), "r"(b[0]), "r"(b[1]));
}
__device__ __forceinline__ void cpa16(uint32_t s, const void* g) {
    asm volatile("cp.async.ca.shared.global [%0], [%1], 16;" :: "r"(s), "l"(g));
}
__device__ __forceinline__ void cpcommit() {
    asm volatile("cp.async.commit_group;" ::: "memory");
}
__device__ __forceinline__ void cpwait1() {
    asm volatile("cp.async.wait_group 1;" ::: "memory");
}
__device__ __forceinline__ void cpwait0() {
    asm volatile("cp.async.wait_group 0;" ::: "memory");
}
// packed bf16x2 = {lo=a, hi=b}, round-to-nearest-even
__device__ __forceinline__ uint32_t cvt_bf2(float a, float b) {
    uint32_t r;
    asm("cvt.rn.bf16x2.f32 %0, %1, %2;" : "=r"(r) : "f"(b), "f"(a));
    return r;
}

// ---------------- prep: fp32 -> split bf16 ----------------
__global__ void prep_x(const float* __restrict__ x) {
    int i = blockIdx.x * 256 + threadIdx.x;
    float v = x[i];
    __nv_bfloat16 h = __float2bfloat16(v);
    (&g_Xhi[0][0])[i] = h;
    (&g_Xlo[0][0])[i] = __float2bfloat16(v - __bfloat162float(h));
}
__global__ void prep_w(ProjArgs pa) {
    __shared__ float tile[32][33];
    int z = blockIdx.z, head = z >> 1, side = z & 1;
    int k0 = blockIdx.x * 32, n0 = blockIdx.y * 32;
    const float* W = pa.W1[head] + side * ND * NL;
    int t = threadIdx.x, c = t & 31, r4 = (t >> 5) * 4;
#pragma unroll
    for (int q = 0; q < 4; q++) tile[r4 + q][c] = W[(k0 + r4 + q) * NL + n0 + c];
    __syncthreads();
#pragma unroll
    for (int q = 0; q < 4; q++) {
        float v = tile[c][r4 + q];
        __nv_bfloat16 h = __float2bfloat16(v);
        g_Wthi[z][n0 + r4 + q][k0 + c] = h;
        g_Wtlo[z][n0 + r4 + q][k0 + c] = __float2bfloat16(v - __bfloat162float(h));
    }
}
__global__ void prep_w2(const float* __restrict__ W2) {
    int e = blockIdx.x * 256 + threadIdx.x;   // 64*512
    int o = e >> 9, l = e & 511;
    float v = (o < NR) ? W2[l * NR + o] : 0.f;
    __nv_bfloat16 h = __float2bfloat16(v);
    g_W2thi[o][l] = h;
    g_W2tlo[o][l] = __float2bfloat16(v - __bfloat162float(h));
}

// ---------------- projections via mma.sync, 2-stage pipeline ----------------
// grid (8 Mtile, 4 Ntile, 8 z), 256 thr. CTA 128x128, warp 64x32, K chunks of 32.
#define PAD 40
#define PJ_STAGE 20480   // bf16 elements per stage (4 tiles of 128*PAD)
__global__ __launch_bounds__(256, 2) void proj_mma(ProjArgs pa) {
    extern __shared__ __nv_bfloat16 dsm[];
    const int t = threadIdx.x, lane = t & 31, w = t >> 5;
    const int wm = w >> 2, wn = w & 3;          // warp grid 2x4
    const int z = blockIdx.z, head = z >> 1, side = z & 1;
    const int r0 = blockIdx.x * 128, c0 = blockIdx.y * 128;
    const float* __restrict__ b1p = pa.b1[head];

    float acc[4][4][4];
#pragma unroll
    for (int mt = 0; mt < 4; mt++)
#pragma unroll
        for (int nt = 0; nt < 4; nt++) { acc[mt][nt][0]=0.f; acc[mt][nt][1]=0.f; acc[mt][nt][2]=0.f; acc[mt][nt][3]=0.f; }

    const int lrow = t >> 2, lq = (t & 3) * 8;

    auto load_chunk = [&](int kc, int st) {
        __nv_bfloat16* Ah = dsm + st * PJ_STAGE;
        __nv_bfloat16* Al = Ah + 5120;
        __nv_bfloat16* Bh = Ah + 10240;
        __nv_bfloat16* Bl = Ah + 15360;
#pragma unroll
        for (int m = 0; m < 2; m++) {
            int row = lrow + 64 * m;
            cpa16(s2u(Ah + row * PAD + lq), &g_Xhi[r0 + row][kc + lq]);
            cpa16(s2u(Al + row * PAD + lq), &g_Xlo[r0 + row][kc + lq]);
            cpa16(s2u(Bh + row * PAD + lq), &g_Wthi[z][c0 + row][kc + lq]);
            cpa16(s2u(Bl + row * PAD + lq), &g_Wtlo[z][c0 + row][kc + lq]);
        }
        cpcommit();
    };

    load_chunk(0, 0);
    const int NCH = ND / 32;
    for (int c = 0; c < NCH; c++) {
        if (c + 1 < NCH) { load_chunk((c + 1) * 32, (c + 1) & 1); cpwait1(); }
        else cpwait0();
        __syncthreads();
        const __nv_bfloat16* Ah = dsm + (c & 1) * PJ_STAGE;
        const __nv_bfloat16* Al = Ah + 5120;
        const __nv_bfloat16* Bh = Ah + 10240;
        const __nv_bfloat16* Bl = Ah + 15360;
#pragma unroll
        for (int ks = 0; ks < 2; ks++) {
            const int k0 = ks * 16;
            uint32_t ah[4][4], al[4][4], bh[4][2], bl[4][2];
#pragma unroll
            for (int mt = 0; mt < 4; mt++) {
                int ar = wm * 64 + mt * 16 + (lane & 15), ac = k0 + ((lane >> 4) << 3);
                ldm4(ah[mt], s2u(Ah + ar * PAD + ac));
                ldm4(al[mt], s2u(Al + ar * PAD + ac));
            }
#pragma unroll
            for (int nh = 0; nh < 2; nh++) {
                int br = wn * 32 + nh * 16 + ((lane >> 4) << 3) + (lane & 7);
                int bc = k0 + (((lane >> 3) & 1) << 3);
                uint32_t r[4];
                ldm4(r, s2u(Bh + br * PAD + bc));
                bh[nh*2][0]=r[0]; bh[nh*2][1]=r[1]; bh[nh*2+1][0]=r[2]; bh[nh*2+1][1]=r[3];
                ldm4(r, s2u(Bl + br * PAD + bc));
                bl[nh*2][0]=r[0]; bl[nh*2][1]=r[1]; bl[nh*2+1][0]=r[2]; bl[nh*2+1][1]=r[3];
            }
#pragma unroll
            for (int mt = 0; mt < 4; mt++)
#pragma unroll
                for (int nt = 0; nt < 4; nt++) mma_bb(acc[mt][nt], ah[mt], bh[nt]);
#pragma unroll
            for (int mt = 0; mt < 4; mt++)
#pragma unroll
                for (int nt = 0; nt < 4; nt++) mma_bb(acc[mt][nt], ah[mt], bl[nt]);
#pragma unroll
            for (int mt = 0; mt < 4; mt++)
#pragma unroll
                for (int nt = 0; nt < 4; nt++) mma_bb(acc[mt][nt], al[mt], bh[nt]);
        }
        __syncthreads();
    }
#pragma unroll
    for (int mt = 0; mt < 4; mt++)
#pragma unroll
        for (int nt = 0; nt < 4; nt++) {
            int row = r0 + wm * 64 + mt * 16 + (lane >> 2);
            int col = c0 + wn * 32 + nt * 8 + ((lane & 3) << 1);
            float bb0 = 0.f, bb1 = 0.f;
            if (side) { bb0 = __ldg(&b1p[col]); bb1 = __ldg(&b1p[col + 1]); }
            float2 v0 = make_float2(acc[mt][nt][0] + bb0, acc[mt][nt][1] + bb1);
            float2 v1 = make_float2(acc[mt][nt][2] + bb0, acc[mt][nt][3] + bb1);
            *(float2*)&g_P[z][row][col] = v0;
            *(float2*)&g_P[z][row + 8][col] = v1;
        }
}

// ---------------- fused pair-scalar + lab kernel, interleaved flat grid ----------------
// 1D grid of 704 = 64 groups x 11. bid%11 < 3 -> pair (192 blocks), else lab (512).
// Interleaving puts MUFU-heavy pair blocks alongside tensor-heavy lab blocks in
// every resident wave so both pipes run concurrently.
// Dynamic smem 72960 B (lab layout); pair uses first 13440 B.
#define LAB_SMEM 72960
#define O_W2H  0          // bf16 [2][64][40]  = 10240
#define O_W2L  10240      // bf16 [2][64][40]  = 10240
#define O_HH   20480      // bf16 [256][40]    = 20480
#define O_HL   40960      // bf16 [256][40]    = 20480
#define O_LC   61440      // float [2][32][36] = 9216
#define O_RC   70656      // float [2][8][36]  = 2304

__global__ __launch_bounds__(256, 2) void pairlab_kernel(ScalArgs sa,
                                                         const float* __restrict__ b2lab,
                                                         float* __restrict__ out) {
    extern __shared__ __align__(16) char sdyn[];
    const int t = threadIdx.x;
    const int bid = blockIdx.x;
    const int grp = bid / 11, rem = bid - grp * 11;

    if (rem < 3) {
        // ---------------- pair-scalar branch ----------------
        const int pidx = grp * 3 + rem;          // 0..191
        const int head = pidx >> 6, b = (pidx >> 3) & 7, xt = pidx & 7;
        const int it = xt >> 2, jt = xt & 3;
        if (head == 0 && it * 64 + 63 < jt * 32) return;
        const int i0 = it * 64, j0 = jt * 32;
        float (*Ls)[68] = (float(*)[68])sdyn;                 // 8704
        float (*Rs)[36] = (float(*)[36])(sdyn + 8704);        // 4608
        float* w2s = (float*)(sdyn + 13312);                  // 128
        const float* __restrict__ Lg = &g_P[head * 2][b * NS + i0][0];
        const float* __restrict__ Rg = &g_P[head * 2 + 1][b * NS + j0][0];
        const float* __restrict__ w2 = sa.w2[head];
        const int ti4 = (t >> 4) << 2, tj2 = (t & 15) << 1;
        float acc[4][2];
#pragma unroll
        for (int r = 0; r < 4; r++) { acc[r][0] = 0.f; acc[r][1] = 0.f; }
        for (int l0 = 0; l0 < NL; l0 += 32) {
#pragma unroll
            for (int m = 0; m < 8; m++) {
                int e = t + 256 * m, lk = e & 31, i = e >> 5;
                Ls[lk][i] = Lg[i * NL + l0 + lk];
            }
#pragma unroll
            for (int m = 0; m < 4; m++) {
                int e = t + 256 * m, lk = e & 31, j = e >> 5;
                Rs[lk][j] = Rg[j * NL + l0 + lk];
            }
            if (t < 32) w2s[t] = w2[l0 + t];
            __syncthreads();
#pragma unroll
            for (int lk = 0; lk < 32; lk++) {
                float4 xv = *(const float4*)&Ls[lk][ti4];
                float2 yv = *(const float2*)&Rs[lk][tj2];
                float wv = w2s[lk];
                float xs[4] = {xv.x, xv.y, xv.z, xv.w};
#pragma unroll
                for (int r = 0; r < 4; r++) {
                    acc[r][0] = fmaf(tanha(xs[r] + yv.x), wv, acc[r][0]);
                    acc[r][1] = fmaf(tanha(xs[r] + yv.y), wv, acc[r][1]);
                }
            }
            __syncthreads();
        }
        const float bb = sa.b2[head][0];
        float* o = out + head * OUT_HEAD + b * NS * NS;
#pragma unroll
        for (int r = 0; r < 4; r++) {
            o[(i0 + ti4 + r) * NS + j0 + tj2]     = acc[r][0] + bb;
            o[(i0 + ti4 + r) * NS + j0 + tj2 + 1] = acc[r][1] + bb;
        }
        return;
    }

    // ---------------- lab branch: CTA tile 256 pairs x 64 outs ----------------
    const int lidx = grp * 8 + (rem - 3);        // 0..511
    const int lane = t & 31, w = t >> 5;
    const int wm = w >> 1, wn = w & 1;           // warp grid 4x2, warp tile 64x32
    const int b = lidx >> 6;
    const int i0 = ((lidx >> 4) & 3) * 32, j0 = (lidx & 15) * 8;
    float* outl = out + 3 * OUT_HEAD;
    __nv_bfloat16* W2h = (__nv_bfloat16*)(sdyn + O_W2H);   // [st][64][40]
    __nv_bfloat16* W2l = (__nv_bfloat16*)(sdyn + O_W2L);
    __nv_bfloat16* Hh  = (__nv_bfloat16*)(sdyn + O_HH);    // [256][40]
    __nv_bfloat16* Hl  = (__nv_bfloat16*)(sdyn + O_HL);
    float* Lc = (float*)(sdyn + O_LC);                     // [st][32][36]
    float* Rc = (float*)(sdyn + O_RC);                     // [st][8][36]

    float acc[4][4][4];
#pragma unroll
    for (int mt = 0; mt < 4; mt++)
#pragma unroll
        for (int nt = 0; nt < 4; nt++) { acc[mt][nt][0]=0.f; acc[mt][nt][1]=0.f; acc[mt][nt][2]=0.f; acc[mt][nt][3]=0.f; }

    auto load_chunk = [&](int kc, int st) {
        { int row = t >> 3, q = t & 7;       // Lc: 32 rows x 32 floats
          cpa16(s2u(Lc + st * 1152 + row * 36 + q * 4), &g_P[6][b * NS + i0 + row][kc + q * 4]); }
        if (t < 64) { int row = t >> 3, q = t & 7;
          cpa16(s2u(Rc + st * 288 + row * 36 + q * 4), &g_P[7][b * NS + j0 + row][kc + q * 4]); }
        { int row = t >> 2, q = (t & 3) * 8; // W2: 64 rows x 32 bf16
          cpa16(s2u(W2h + st * 2560 + row * PAD + q), &g_W2thi[row][kc + q]);
          cpa16(s2u(W2l + st * 2560 + row * PAD + q), &g_W2tlo[row][kc + q]); }
        cpcommit();
    };

    load_chunk(0, 0);
    const int NCH = NL / 32;
    for (int c = 0; c < NCH; c++) {
        const int st = c & 1;
        if (c + 1 < NCH) { load_chunk((c + 1) * 32, (c + 1) & 1); cpwait1(); }
        else cpwait0();
        __syncthreads();
        // tanh + split: thread t <-> pair t, 32 k per chunk
        {
            const float* Lr = Lc + st * 1152 + (t >> 3) * 36;
            const float* Rr = Rc + st * 288 + (t & 7) * 36;
#pragma unroll
            for (int qq = 0; qq < 4; qq++) {
                uint32_t hv[4], lv[4];
#pragma unroll
                for (int e2 = 0; e2 < 2; e2++) {
                    int k = qq * 8 + e2 * 4;
                    float4 lx = *(const float4*)&Lr[k];
                    float4 rx = *(const float4*)&Rr[k];
                    float h0 = tanha(lx.x + rx.x), h1 = tanha(lx.y + rx.y);
                    float h2 = tanha(lx.z + rx.z), h3 = tanha(lx.w + rx.w);
                    uint32_t u01 = cvt_bf2(h0, h1);
                    uint32_t u23 = cvt_bf2(h2, h3);
                    float g0 = __uint_as_float(u01 << 16);
                    float g1 = __uint_as_float(u01 & 0xffff0000u);
                    float g2 = __uint_as_float(u23 << 16);
                    float g3 = __uint_as_float(u23 & 0xffff0000u);
                    hv[e2*2]   = u01; hv[e2*2+1] = u23;
                    lv[e2*2]   = cvt_bf2(h0 - g0, h1 - g1);
                    lv[e2*2+1] = cvt_bf2(h2 - g2, h3 - g3);
                }
                *(uint4*)(Hh + t * PAD + qq * 8) = make_uint4(hv[0], hv[1], hv[2], hv[3]);
                *(uint4*)(Hl + t * PAD + qq * 8) = make_uint4(lv[0], lv[1], lv[2], lv[3]);
            }
        }
        __syncthreads();
#pragma unroll
        for (int ks = 0; ks < 2; ks++) {
            const int k0 = ks * 16;
            uint32_t ah[4][4], al[4][4], bh[4][2], bl[4][2];
#pragma unroll
            for (int mt = 0; mt < 4; mt++) {
                int ar = wm * 64 + mt * 16 + (lane & 15), ac = k0 + ((lane >> 4) << 3);
                ldm4(ah[mt], s2u(Hh + ar * PAD + ac));
                ldm4(al[mt], s2u(Hl + ar * PAD + ac));
            }
#pragma unroll
            for (int nh = 0; nh < 2; nh++) {
                int br = wn * 32 + nh * 16 + ((lane >> 4) << 3) + (lane & 7);
                int bc = k0 + (((lane >> 3) & 1) << 3);
                uint32_t r[4];
                ldm4(r, s2u(W2h + st * 2560 + br * PAD + bc));
                bh[nh*2][0]=r[0]; bh[nh*2][1]=r[1]; bh[nh*2+1][0]=r[2]; bh[nh*2+1][1]=r[3];
                ldm4(r, s2u(W2l + st * 2560 + br * PAD + bc));
                bl[nh*2][0]=r[0]; bl[nh*2][1]=r[1]; bl[nh*2+1][0]=r[2]; bl[nh*2+1][1]=r[3];
            }
#pragma unroll
            for (int mt = 0; mt < 4; mt++)
#pragma unroll
                for (int nt = 0; nt < 4; nt++) mma_bb(acc[mt][nt], ah[mt], bh[nt]);
#pragma unroll
            for (int mt = 0; mt < 4; mt++)
#pragma unroll
                for (int nt = 0; nt < 4; nt++) mma_bb(acc[mt][nt], ah[mt], bl[nt]);
#pragma unroll
            for (int mt = 0; mt < 4; mt++)
#pragma unroll
                for (int nt = 0; nt < 4; nt++) mma_bb(acc[mt][nt], al[mt], bh[nt]);
        }
        __syncthreads();
    }
#pragma unroll
    for (int mt = 0; mt < 4; mt++)
#pragma unroll
        for (int nt = 0; nt < 4; nt++) {
            int o = wn * 32 + nt * 8 + ((lane & 3) << 1);
            if (o < NR) {
                float bb0 = __ldg(&b2lab[o]), bb1 = __ldg(&b2lab[o + 1]);
#pragma unroll
                for (int half = 0; half < 2; half++) {
                    int pp = wm * 64 + mt * 16 + (lane >> 2) + half * 8;
                    int i = i0 + (pp >> 3), j = j0 + (pp & 7);
                    float2 v = make_float2(acc[mt][nt][half*2] + bb0,
                                           acc[mt][nt][half*2+1] + bb1);
                    *(float2*)&outl[((b * NS + i) * NS + j) * NR + o] = v;
                }
            }
        }
}

__global__ void sym_kernel(float* __restrict__ out) {
    int idx = blockIdx.x * 256 + threadIdx.x;
    int b = idx >> 14, r = idx & 16383, i = r >> 7, j = r & 127;
    if (i < j) out[idx] = out[(b << 14) + (j << 7) + i];
}

// ---------------------------------------------------------------------------
extern "C" void kernel_launch(void* const* d_in, const int* in_sizes, int n_in,
                              void* d_out, int out_size) {
    (void)in_sizes; (void)n_in; (void)out_size;
    const float* x = (const float*)d_in[0];
    ProjArgs pa;
    pa.W1[0] = (const float*)d_in[1];  pa.b1[0] = (const float*)d_in[2];
    pa.W1[1] = (const float*)d_in[5];  pa.b1[1] = (const float*)d_in[6];
    pa.W1[2] = (const float*)d_in[9];  pa.b1[2] = (const float*)d_in[10];
    pa.W1[3] = (const float*)d_in[13]; pa.b1[3] = (const float*)d_in[14];
    ScalArgs sa;
    sa.w2[0] = (const float*)d_in[3];  sa.b2[0] = (const float*)d_in[4];
    sa.w2[1] = (const float*)d_in[7];  sa.b2[1] = (const float*)d_in[8];
    sa.w2[2] = (const float*)d_in[11]; sa.b2[2] = (const float*)d_in[12];
    float* out = (float*)d_out;

    static int configured = 0;
    if (!configured) {
        cudaFuncSetAttribute(proj_mma, cudaFuncAttributeMaxDynamicSharedMemorySize,
                             2 * PJ_STAGE * (int)sizeof(__nv_bfloat16));
        cudaFuncSetAttribute(pairlab_kernel, cudaFuncAttributeMaxDynamicSharedMemorySize,
                             LAB_SMEM);
        configured = 1;
    }

    prep_x<<<2048, 256>>>(x);
    prep_w<<<dim3(16, 16, 8), 256>>>(pa);
    prep_w2<<<128, 256>>>((const float*)d_in[15]);

    proj_mma<<<dim3(8, 4, 8), 256, 2 * PJ_STAGE * (int)sizeof(__nv_bfloat16)>>>(pa);

    pairlab_kernel<<<704, 256, LAB_SMEM>>>(sa, (const float*)d_in[16], out);

    sym_kernel<<<512, 256>>>(out);
}